// round 14
// baseline (speedup 1.0000x reference)
#include <cuda_runtime.h>

#define N_NODES 100000
#define N_EDGES 3200000
#define F_IN    512
#define NH      16
#define NC      3

// ---------------- scratch (device globals; device-code references ONLY) -----
__device__ int   g_deg_out[N_NODES];
__device__ int   g_deg_in [N_NODES];
__device__ float g_norm_src[N_NODES];
__device__ float g_norm_dst[N_NODES];
__device__ int   g_row_start[N_NODES + 1];
__device__ int   g_cursor[N_NODES];
__device__ int   g_csr_src[N_EDGES];              // src ids grouped by dst
__device__ float g_h1[(size_t)N_NODES * NH];      // feat@W1, then *= ns
__device__ float g_y [(size_t)N_NODES * 4];       // (relu(agg1*nd+b1)*ns)@W2f
__device__ float g_W2f[NH * NC];                  // W2 @ Wfc
__device__ float g_b2f[NC];                       // b2 @ Wfc + bfc
__device__ int   g_idx64;                         // 1 if indices are int64

// ---------------- index dtype detection (int64 vs int32) --------------------
__global__ void k_detect(const int* __restrict__ src_as_i32) {
    int any = 0;
    #pragma unroll
    for (int j = 0; j < 64; j++) any |= src_as_i32[2 * j + 1];
    g_idx64 = (any == 0) ? 1 : 0;
}

__device__ __forceinline__ int load_idx(const void* p, int i, int is64) {
    return is64 ? (int)((const long long*)p)[i] : ((const int*)p)[i];
}

// ---------------- zero degree counters (side stream) -------------------------
__global__ void k_zero() {
    int i = blockIdx.x * blockDim.x + threadIdx.x;
    if (i < N_NODES) { g_deg_out[i] = 0; g_deg_in[i] = 0; }
}

// ---------------- degree histogram (side stream) -----------------------------
__global__ __launch_bounds__(256)
void k_deg(const void* __restrict__ src, const void* __restrict__ dst) {
    int is64 = g_idx64;
    int stride = gridDim.x * blockDim.x;
    for (int i = blockIdx.x * blockDim.x + threadIdx.x; i < N_EDGES; i += stride) {
        int s = load_idx(src, i, is64);
        int d = load_idx(dst, i, is64);
        asm volatile("red.global.add.u32 [%0], %1;"
                     :: "l"(g_deg_out + s), "r"(1) : "memory");
        asm volatile("red.global.add.u32 [%0], %1;"
                     :: "l"(g_deg_in + d), "r"(1) : "memory");
    }
}

// ---------------- norms (side stream) ----------------------------------------
__global__ void k_norm() {
    int n = blockIdx.x * blockDim.x + threadIdx.x;
    if (n >= N_NODES) return;
    g_norm_src[n] = rsqrtf(fmaxf((float)g_deg_out[n], 1.f));
    g_norm_dst[n] = rsqrtf(fmaxf((float)g_deg_in [n], 1.f));
}

// ---------------- exclusive scan deg_in -> row_start (+cursor), 1 block ------
__global__ __launch_bounds__(1024)
void k_scan() {
    __shared__ int sp[1024];
    const int CH = (N_NODES + 1023) / 1024;       // 98
    int tid = threadIdx.x;
    int base = tid * CH;
    int end  = min(base + CH, N_NODES);

    int s = 0;
    for (int j = base; j < end; j++) s += g_deg_in[j];
    sp[tid] = s;
    __syncthreads();
    #pragma unroll
    for (int off = 1; off < 1024; off <<= 1) {
        int v = (tid >= off) ? sp[tid - off] : 0;
        __syncthreads();
        sp[tid] += v;
        __syncthreads();
    }
    int run = sp[tid] - s;                         // exclusive prefix
    for (int j = base; j < end; j++) {
        g_row_start[j] = run;
        g_cursor[j]    = run;
        run += g_deg_in[j];
    }
    if (tid == 0) g_row_start[N_NODES] = N_EDGES;
}

// ---------------- fill CSR (side stream, hidden under gemm1) -----------------
__global__ void k_fill(const void* __restrict__ src, const void* __restrict__ dst) {
    int i = blockIdx.x * blockDim.x + threadIdx.x;
    if (i >= N_EDGES) return;
    int is64 = g_idx64;
    int s = load_idx(src, i, is64);
    int d = load_idx(dst, i, is64);
    int slot = atomicAdd(&g_cursor[d], 1);
    g_csr_src[slot] = s;
}

// ---------------- GEMM1: h1 = feat @ W1  (register-direct features) ----------
#define GB3 64
#define RED_STRIDE 18
#define SMEM3 ((F_IN * NH + 8 * GB3 * RED_STRIDE) * 4)

__global__ __launch_bounds__(256, 2)
void k_gemm1(const float* __restrict__ feat, const float* __restrict__ W1) {
    extern __shared__ float smem[];
    float* sW   = smem;                           // [512][16]
    float* sRed = smem + F_IN * NH;               // [8*64][18]

    const int tid  = threadIdx.x;
    const int w    = tid >> 5;
    const int lane = tid & 31;
    const int n0   = blockIdx.x * GB3;

    #pragma unroll
    for (int t = tid; t < F_IN * NH / 4; t += 256)
        ((float4*)sW)[t] = ((const float4*)W1)[t];
    __syncthreads();

    const int na = n0 + lane;
    const int nb = n0 + 32 + lane;
    const float* ra = feat + (size_t)(na < N_NODES ? na : N_NODES - 1) * F_IN;
    const float* rb = feat + (size_t)(nb < N_NODES ? nb : N_NODES - 1) * F_IN;
    const int kw = w * 8;

    float4 a0 = *(const float4*)(ra + kw);
    float4 a1 = *(const float4*)(ra + kw + 4);
    float4 b0 = *(const float4*)(rb + kw);
    float4 b1 = *(const float4*)(rb + kw + 4);

    unsigned long long A[8] = {0,0,0,0,0,0,0,0};
    unsigned long long B[8] = {0,0,0,0,0,0,0,0};

    #pragma unroll
    for (int c = 0; c < 8; c++) {
        float4 na0, na1, nb0, nb1;
        if (c < 7) {
            int ko = (c + 1) * 64 + kw;
            na0 = *(const float4*)(ra + ko);
            na1 = *(const float4*)(ra + ko + 4);
            nb0 = *(const float4*)(rb + ko);
            nb1 = *(const float4*)(rb + ko + 4);
        }
        float pa[8], pb[8];
        *(float4*)&pa[0] = a0; *(float4*)&pa[4] = a1;
        *(float4*)&pb[0] = b0; *(float4*)&pb[4] = b1;

        const float* wk = sW + (size_t)(c * 64 + kw) * NH;
        #pragma unroll
        for (int j = 0; j < 8; j++) {
            unsigned long long fa, fb;
            asm("mov.b64 %0, {%1, %1};" : "=l"(fa) : "f"(pa[j]));
            asm("mov.b64 %0, {%1, %1};" : "=l"(fb) : "f"(pb[j]));
            const ulonglong2* wp = (const ulonglong2*)(wk + j * NH);
            ulonglong2 w0 = wp[0], w1 = wp[1];
            const ulonglong2* wq = (const ulonglong2*)(wk + j * NH + 8);
            ulonglong2 w2 = wq[0], w3 = wq[1];
            asm("fma.rn.f32x2 %0, %1, %2, %0;" : "+l"(A[0]) : "l"(fa), "l"(w0.x));
            asm("fma.rn.f32x2 %0, %1, %2, %0;" : "+l"(A[1]) : "l"(fa), "l"(w0.y));
            asm("fma.rn.f32x2 %0, %1, %2, %0;" : "+l"(A[2]) : "l"(fa), "l"(w1.x));
            asm("fma.rn.f32x2 %0, %1, %2, %0;" : "+l"(A[3]) : "l"(fa), "l"(w1.y));
            asm("fma.rn.f32x2 %0, %1, %2, %0;" : "+l"(A[4]) : "l"(fa), "l"(w2.x));
            asm("fma.rn.f32x2 %0, %1, %2, %0;" : "+l"(A[5]) : "l"(fa), "l"(w2.y));
            asm("fma.rn.f32x2 %0, %1, %2, %0;" : "+l"(A[6]) : "l"(fa), "l"(w3.x));
            asm("fma.rn.f32x2 %0, %1, %2, %0;" : "+l"(A[7]) : "l"(fa), "l"(w3.y));
            asm("fma.rn.f32x2 %0, %1, %2, %0;" : "+l"(B[0]) : "l"(fb), "l"(w0.x));
            asm("fma.rn.f32x2 %0, %1, %2, %0;" : "+l"(B[1]) : "l"(fb), "l"(w0.y));
            asm("fma.rn.f32x2 %0, %1, %2, %0;" : "+l"(B[2]) : "l"(fb), "l"(w1.x));
            asm("fma.rn.f32x2 %0, %1, %2, %0;" : "+l"(B[3]) : "l"(fb), "l"(w1.y));
            asm("fma.rn.f32x2 %0, %1, %2, %0;" : "+l"(B[4]) : "l"(fb), "l"(w2.x));
            asm("fma.rn.f32x2 %0, %1, %2, %0;" : "+l"(B[5]) : "l"(fb), "l"(w2.y));
            asm("fma.rn.f32x2 %0, %1, %2, %0;" : "+l"(B[6]) : "l"(fb), "l"(w3.x));
            asm("fma.rn.f32x2 %0, %1, %2, %0;" : "+l"(B[7]) : "l"(fb), "l"(w3.y));
        }
        a0 = na0; a1 = na1; b0 = nb0; b1 = nb1;
    }

    __syncthreads();
    {
        float* pa = sRed + (size_t)(w * 64 + lane) * RED_STRIDE;
        float* pb = sRed + (size_t)(w * 64 + 32 + lane) * RED_STRIDE;
        #pragma unroll
        for (int i = 0; i < 8; i++) {
            *(float2*)&pa[2 * i] = *(float2*)&A[i];
            *(float2*)&pb[2 * i] = *(float2*)&B[i];
        }
    }
    __syncthreads();
    #pragma unroll
    for (int t = tid; t < GB3 * 8; t += 256) {
        int node = t >> 3, p = t & 7;
        float sx = 0.f, sy = 0.f;
        #pragma unroll
        for (int ww = 0; ww < 8; ww++) {
            float2 v = *(float2*)&sRed[(size_t)(ww * 64 + node) * RED_STRIDE + 2 * p];
            sx += v.x; sy += v.y;
        }
        int n = n0 + node;
        if (n < N_NODES)
            *(float2*)&g_h1[(size_t)n * NH + 2 * p] = make_float2(sx, sy);
    }
}

// ---------------- scale h1 by norm_src (once) --------------------------------
__global__ void k_scale() {
    int i = blockIdx.x * blockDim.x + threadIdx.x;
    if (i >= N_NODES * 4) return;
    float ns = g_norm_src[i >> 2];
    float4 v = ((const float4*)g_h1)[i];
    v.x *= ns; v.y *= ns; v.z *= ns; v.w *= ns;
    ((float4*)g_h1)[i] = v;
}

// ---------------- W2f = W2 @ Wfc, b2f = b2 @ Wfc + bfc  (warp-parallel) ------
__global__ void k_w2f(const float* __restrict__ W2, const float* __restrict__ b2,
                      const float* __restrict__ Wfc, const float* __restrict__ bfc) {
    int w    = (blockIdx.x * blockDim.x + threadIdx.x) >> 5;
    int lane = threadIdx.x & 31;
    if (w < NH * NC) {
        int h = w / NC, c = w % NC;
        float s = 0.f;
        #pragma unroll
        for (int k = lane; k < 128; k += 32)
            s = fmaf(__ldg(W2 + h * 128 + k), __ldg(Wfc + k * NC + c), s);
        #pragma unroll
        for (int m = 16; m; m >>= 1) s += __shfl_xor_sync(0xffffffffu, s, m);
        if (lane == 0) g_W2f[w] = s;
    } else if (w < NH * NC + NC) {
        int c = w - NH * NC;
        float s = 0.f;
        #pragma unroll
        for (int k = lane; k < 128; k += 32)
            s = fmaf(__ldg(b2 + k), __ldg(Wfc + k * NC + c), s);
        #pragma unroll
        for (int m = 16; m; m >>= 1) s += __shfl_xor_sync(0xffffffffu, s, m);
        if (lane == 0) g_b2f[c] = s + __ldg(bfc + c);
    }
}

// ---------------- gather1: y[n] = (relu((Σ h1s[src])*nd + b1)*ns) @ W2f ------
// Warp per node. Lanes: q=lane&3 owns float4 quad; e=lane>>2 strides edges
// by 8 (4 q-lanes read one contiguous 64B h1 row -> coalesced L2 gather).
__global__ __launch_bounds__(256)
void k_gather1(const float* __restrict__ b1) {
    __shared__ float sw[NH * NC];
    if (threadIdx.x < NH * NC) sw[threadIdx.x] = g_W2f[threadIdx.x];
    __syncthreads();
    int warp = blockIdx.x * 8 + (threadIdx.x >> 5);
    int lane = threadIdx.x & 31;
    if (warp >= N_NODES) return;
    int rs = g_row_start[warp];
    int re = g_row_start[warp + 1];
    int q  = lane & 3;
    float4 acc = make_float4(0.f, 0.f, 0.f, 0.f);
    #pragma unroll 2
    for (int j = rs + (lane >> 2); j < re; j += 8) {
        int s = g_csr_src[j];
        float4 v = __ldg((const float4*)(g_h1 + (size_t)s * NH) + q);
        acc.x += v.x; acc.y += v.y; acc.z += v.z; acc.w += v.w;
    }
    #pragma unroll
    for (int m = 4; m <= 16; m <<= 1) {            // reduce across edge groups
        acc.x += __shfl_xor_sync(0xffffffffu, acc.x, m);
        acc.y += __shfl_xor_sync(0xffffffffu, acc.y, m);
        acc.z += __shfl_xor_sync(0xffffffffu, acc.z, m);
        acc.w += __shfl_xor_sync(0xffffffffu, acc.w, m);
    }
    // every lane now holds quad (lane&3) totals; fused relu + W2f projection
    float nd = g_norm_dst[warp];
    float ns = g_norm_src[warp];
    float4 b = __ldg((const float4*)b1 + q);
    float x0 = fmaxf(fmaf(acc.x, nd, b.x), 0.f) * ns;
    float x1 = fmaxf(fmaf(acc.y, nd, b.y), 0.f) * ns;
    float x2 = fmaxf(fmaf(acc.z, nd, b.z), 0.f) * ns;
    float x3 = fmaxf(fmaf(acc.w, nd, b.w), 0.f) * ns;
    int h0 = q * 4;
    float s0 = x0*sw[(h0+0)*3+0] + x1*sw[(h0+1)*3+0] + x2*sw[(h0+2)*3+0] + x3*sw[(h0+3)*3+0];
    float s1 = x0*sw[(h0+0)*3+1] + x1*sw[(h0+1)*3+1] + x2*sw[(h0+2)*3+1] + x3*sw[(h0+3)*3+1];
    float s2 = x0*sw[(h0+0)*3+2] + x1*sw[(h0+1)*3+2] + x2*sw[(h0+2)*3+2] + x3*sw[(h0+3)*3+2];
    #pragma unroll
    for (int m = 1; m <= 2; m <<= 1) {             // reduce across 4 q-lanes
        s0 += __shfl_xor_sync(0xffffffffu, s0, m);
        s1 += __shfl_xor_sync(0xffffffffu, s1, m);
        s2 += __shfl_xor_sync(0xffffffffu, s2, m);
    }
    if (lane == 0)
        ((float4*)g_y)[warp] = make_float4(s0, s1, s2, 0.f);
}

// ---------------- gather2: out[n] = nd * Σ y[src] + b2f ----------------------
// Warp per node; each lane handles one edge (float4 y row), butterfly reduce.
__global__ __launch_bounds__(256)
void k_gather2(float* __restrict__ out) {
    int warp = blockIdx.x * 8 + (threadIdx.x >> 5);
    int lane = threadIdx.x & 31;
    if (warp >= N_NODES) return;
    int rs = g_row_start[warp];
    int re = g_row_start[warp + 1];
    float s0 = 0.f, s1 = 0.f, s2 = 0.f;
    for (int j = rs + lane; j < re; j += 32) {
        int s = g_csr_src[j];
        float4 v = __ldg((const float4*)g_y + s);
        s0 += v.x; s1 += v.y; s2 += v.z;
    }
    #pragma unroll
    for (int m = 16; m; m >>= 1) {
        s0 += __shfl_xor_sync(0xffffffffu, s0, m);
        s1 += __shfl_xor_sync(0xffffffffu, s1, m);
        s2 += __shfl_xor_sync(0xffffffffu, s2, m);
    }
    if (lane == 0) {
        float nd = g_norm_dst[warp];
        out[(size_t)warp * 3 + 0] = fmaf(nd, s0, g_b2f[0]);
        out[(size_t)warp * 3 + 1] = fmaf(nd, s1, g_b2f[1]);
        out[(size_t)warp * 3 + 2] = fmaf(nd, s2, g_b2f[2]);
    }
}

// ---------------- launch ------------------------------------------------------
extern "C" void kernel_launch(void* const* d_in, const int* in_sizes, int n_in,
                              void* d_out, int out_size) {
    const float* feat = (const float*)d_in[0];
    const void*  src  = d_in[1];
    const void*  dst  = d_in[2];
    const float* W1   = (const float*)d_in[3];
    const float* b1   = (const float*)d_in[4];
    const float* W2   = (const float*)d_in[5];
    const float* b2   = (const float*)d_in[6];
    const float* Wfc  = (const float*)d_in[7];
    const float* bfc  = (const float*)d_in[8];
    float* out = (float*)d_out;

    static cudaStream_t s1 = nullptr;
    static cudaEvent_t  e0 = nullptr, e1 = nullptr;
    if (!s1) {
        cudaStreamCreateWithFlags(&s1, cudaStreamNonBlocking);
        cudaEventCreateWithFlags(&e0, cudaEventDisableTiming);
        cudaEventCreateWithFlags(&e1, cudaEventDisableTiming);
        cudaFuncSetAttribute(k_gemm1, cudaFuncAttributeMaxDynamicSharedMemorySize,
                             SMEM3);
    }

    const int EB = (N_EDGES + 255) / 256;            // 12500
    const int NB = (N_NODES + 255) / 256;            // 391
    const int GBLK = (N_NODES + GB3 - 1) / GB3;      // 1563

    k_detect<<<1, 1>>>((const int*)src);             // #1
    cudaEventRecord(e0, 0);

    cudaStreamWaitEvent(s1, e0, 0);
    k_zero<<<NB, 256, 0, s1>>>();                    // #2
    k_deg <<<2048, 256, 0, s1>>>(src, dst);          // #3

    k_gemm1<<<GBLK, 256, SMEM3>>>(feat, W1);         // #4  <- profiled

    // side stream: CSR build + norms + W2f, all hidden under gemm1
    k_norm<<<NB, 256, 0, s1>>>();                    // #5
    k_scan<<<1, 1024, 0, s1>>>();                    // #6
    k_fill<<<EB, 256, 0, s1>>>(src, dst);            // #7
    k_w2f <<<2, 1024, 0, s1>>>(W2, b2, Wfc, bfc);    // #8
    cudaEventRecord(e1, s1);

    cudaStreamWaitEvent(0, e1, 0);
    k_scale  <<<(N_NODES * 4 + 255) / 256, 256>>>(); // #9
    k_gather1<<<12500, 256>>>(b1);                   // #10
    k_gather2<<<12500, 256>>>(out);                  // #11
}

// round 15
// speedup vs baseline: 1.6747x; 1.6747x over previous
#include <cuda_runtime.h>

#define N_NODES 100000
#define N_EDGES 3200000
#define F_IN    512
#define NH      16
#define NC      3

// ---------------- scratch (device globals; device-code references ONLY) -----
__device__ int   g_deg_out[N_NODES];
__device__ int   g_deg_in [N_NODES];
__device__ float g_norm_src[N_NODES];
__device__ float g_norm_dst[N_NODES];
__device__ int2  g_edge[N_EDGES];                 // packed (src,dst) int32
__device__ float g_h1  [(size_t)N_NODES * NH];    // feat@W1 (unscaled)
__device__ float g_agg1[(size_t)N_NODES * NH];
__device__ float g_y   [(size_t)N_NODES * 4];     // (relu(agg1*nd+b1)*ns)@W2f
__device__ float g_agg2[(size_t)N_NODES * 4];
__device__ float g_W2f [NH * NC];                 // W2 @ Wfc
__device__ float g_b2f [NC];                      // b2 @ Wfc + bfc
__device__ int   g_idx64;                         // 1 if indices are int64

// ---------------- index dtype detection (int64 vs int32) --------------------
__global__ void k_detect(const int* __restrict__ src_as_i32) {
    int any = 0;
    #pragma unroll
    for (int j = 0; j < 64; j++) any |= src_as_i32[2 * j + 1];
    g_idx64 = (any == 0) ? 1 : 0;
}

__device__ __forceinline__ int load_idx(const void* p, int i, int is64) {
    return is64 ? (int)((const long long*)p)[i] : ((const int*)p)[i];
}

// ---------------- zero accumulators (side stream) ----------------------------
__global__ void k_zero() {
    int i = blockIdx.x * blockDim.x + threadIdx.x;
    if (i < N_NODES * NH) g_agg1[i] = 0.f;
    if (i < N_NODES * 4)  g_agg2[i] = 0.f;
    if (i < N_NODES) { g_deg_out[i] = 0; g_deg_in[i] = 0; }
}

// ---------------- degree histogram + edge compaction (side stream) -----------
__global__ __launch_bounds__(256)
void k_deg(const void* __restrict__ src, const void* __restrict__ dst) {
    int is64 = g_idx64;
    int stride = gridDim.x * blockDim.x;
    for (int i = blockIdx.x * blockDim.x + threadIdx.x; i < N_EDGES; i += stride) {
        int s = load_idx(src, i, is64);
        int d = load_idx(dst, i, is64);
        g_edge[i] = make_int2(s, d);
        asm volatile("red.global.add.u32 [%0], %1;"
                     :: "l"(g_deg_out + s), "r"(1) : "memory");
        asm volatile("red.global.add.u32 [%0], %1;"
                     :: "l"(g_deg_in + d), "r"(1) : "memory");
    }
}

// ---------------- norms (side stream) ----------------------------------------
__global__ void k_norm() {
    int n = blockIdx.x * blockDim.x + threadIdx.x;
    if (n >= N_NODES) return;
    g_norm_src[n] = rsqrtf(fmaxf((float)g_deg_out[n], 1.f));
    g_norm_dst[n] = rsqrtf(fmaxf((float)g_deg_in [n], 1.f));
}

// ---------------- GEMM1: h1 = feat @ W1  (cp.async node-major + broadcast W) --
// 128 nodes/block, 256 thr = 8 warps; warp w owns k-slice [w*8, w*8+8) of each
// 64-wide chunk; lane covers nodes lane+32m (m=0..3).
// Global side: cp.async per instr covers 2 FULL 256B rows -> 4 wavefronts/instr
//   (R13's register-direct LDG: 32 wavefronts/instr -- the 86% L1 culprit).
// smem f: LDS.128 at float4-pitch 17 -> (node+c4) mod 8 hits every 16B bank
//   group exactly 4x = 4-phase floor, no conflict penalty.
// W: warp-uniform LDS.128 broadcasts (1 phase), f float4s held across 4-k block.
// Net ~0.5 L1TEX phases per FFMA2 (R13: ~1.25). Cross-warp reduce at the end.
#define GB4    128
#define PITCH4 17                                  // float4 pitch of staged rows
#define BUF_F4 (GB4 * PITCH4)                      // 2176 float4 per buffer
#define RED_ST 18
#define SMEM4  ((F_IN * NH + 8 * GB4 * RED_ST) * 4)  // 32KB W + 72KB buf/red

__global__ __launch_bounds__(256, 2)
void k_gemm1(const float* __restrict__ feat, const float* __restrict__ W1) {
    extern __shared__ float smem[];
    float*  sW   = smem;                           // [512][16]
    float4* sF   = (float4*)(smem + F_IN * NH);    // 2 x [128][17] float4
    float*  sRed = smem + F_IN * NH;               // [8*128][18] (aliases sF)

    const int tid  = threadIdx.x;
    const int w    = tid >> 5;
    const int lane = tid & 31;
    const int n0   = blockIdx.x * GB4;

    // W1 -> smem (coalesced float4)
    #pragma unroll
    for (int t = tid; t < F_IN * NH / 4; t += 256)
        ((float4*)sW)[t] = ((const float4*)W1)[t];

    // stage chunk c into buffer buf: 2048 float4, node-major (2 rows/instr)
    auto stage = [&](int c, int buf) {
        #pragma unroll
        for (int j = 0; j < 8; j++) {
            int f4idx = tid + 256 * j;
            int node  = f4idx >> 4;                // 0..127
            int c4    = f4idx & 15;                // 0..15
            int n     = n0 + node;
            const float* gsrc = feat +
                (size_t)(n < N_NODES ? n : 0) * F_IN + c * 64 + c4 * 4;
            unsigned sa = (unsigned)__cvta_generic_to_shared(
                &sF[buf * BUF_F4 + node * PITCH4 + c4]);
            int sz = (n < N_NODES) ? 16 : 0;       // 0 => zero-fill
            asm volatile("cp.async.cg.shared.global [%0], [%1], 16, %2;"
                         :: "r"(sa), "l"(gsrc), "r"(sz) : "memory");
        }
        asm volatile("cp.async.commit_group;" ::: "memory");
    };

    stage(0, 0);

    unsigned long long A[4][8];                    // [m][out-pair]
    #pragma unroll
    for (int m = 0; m < 4; m++)
        #pragma unroll
        for (int p = 0; p < 8; p++) A[m][p] = 0ull;

    #pragma unroll
    for (int c = 0; c < 8; c++) {
        if (c < 7) {
            stage(c + 1, (c + 1) & 1);
            asm volatile("cp.async.wait_group 1;" ::: "memory");
        } else {
            asm volatile("cp.async.wait_group 0;" ::: "memory");
        }
        __syncthreads();                           // buf c visible; prev buf free

        const float4* fb = sF + (c & 1) * BUF_F4;
        #pragma unroll
        for (int c4i = 0; c4i < 2; c4i++) {
            const int c4 = w * 2 + c4i;            // this warp's f4 column
            // hold 4 nodes' float4 for this 4-k group
            float f[4][4];
            #pragma unroll
            for (int m = 0; m < 4; m++) {
                float4 v = fb[(lane + 32 * m) * PITCH4 + c4];
                f[m][0] = v.x; f[m][1] = v.y; f[m][2] = v.z; f[m][3] = v.w;
            }
            const float* wk = sW + (size_t)(c * 64 + c4 * 4) * NH;
            #pragma unroll
            for (int kk = 0; kk < 4; kk++) {
                const ulonglong2* wp = (const ulonglong2*)(wk + kk * NH);
                ulonglong2 w0 = wp[0], w1 = wp[1]; // broadcast LDS.128
                const ulonglong2* wq = (const ulonglong2*)(wk + kk * NH + 8);
                ulonglong2 w2 = wq[0], w3 = wq[1]; // broadcast LDS.128
                #pragma unroll
                for (int m = 0; m < 4; m++) {
                    unsigned long long fp;
                    asm("mov.b64 %0, {%1, %1};" : "=l"(fp) : "f"(f[m][kk]));
                    asm("fma.rn.f32x2 %0, %1, %2, %0;" : "+l"(A[m][0]) : "l"(fp), "l"(w0.x));
                    asm("fma.rn.f32x2 %0, %1, %2, %0;" : "+l"(A[m][1]) : "l"(fp), "l"(w0.y));
                    asm("fma.rn.f32x2 %0, %1, %2, %0;" : "+l"(A[m][2]) : "l"(fp), "l"(w1.x));
                    asm("fma.rn.f32x2 %0, %1, %2, %0;" : "+l"(A[m][3]) : "l"(fp), "l"(w1.y));
                    asm("fma.rn.f32x2 %0, %1, %2, %0;" : "+l"(A[m][4]) : "l"(fp), "l"(w2.x));
                    asm("fma.rn.f32x2 %0, %1, %2, %0;" : "+l"(A[m][5]) : "l"(fp), "l"(w2.y));
                    asm("fma.rn.f32x2 %0, %1, %2, %0;" : "+l"(A[m][6]) : "l"(fp), "l"(w3.x));
                    asm("fma.rn.f32x2 %0, %1, %2, %0;" : "+l"(A[m][7]) : "l"(fp), "l"(w3.y));
                }
            }
        }
        __syncthreads();                           // done with buf c
    }

    // cross-warp reduce (sRed aliases the staging buffers -- compute is done)
    #pragma unroll
    for (int m = 0; m < 4; m++) {
        float* dst = sRed + (size_t)(w * GB4 + lane + 32 * m) * RED_ST;
        #pragma unroll
        for (int p = 0; p < 8; p++)
            *(float2*)&dst[2 * p] = *(float2*)&A[m][p];
    }
    __syncthreads();
    #pragma unroll
    for (int t = tid; t < GB4 * 8; t += 256) {     // (node, out-pair) tasks
        int node = t >> 3, p = t & 7;
        float sx = 0.f, sy = 0.f;
        #pragma unroll
        for (int ww = 0; ww < 8; ww++) {
            float2 v = *(float2*)&sRed[(size_t)(ww * GB4 + node) * RED_ST + 2 * p];
            sx += v.x; sy += v.y;
        }
        int n = n0 + node;
        if (n < N_NODES)
            *(float2*)&g_h1[(size_t)n * NH + 2 * p] = make_float2(sx, sy);
    }
}

// ---------------- edge pass 1: agg1[d] += ns[s]*h1[s]  (4x RED.128) ----------
__device__ __forceinline__ void red4(float* p, float4 v) {
    asm volatile("red.global.add.v4.f32 [%0], {%1,%2,%3,%4};"
                 :: "l"(p), "f"(v.x), "f"(v.y), "f"(v.z), "f"(v.w) : "memory");
}

__global__ void k_edge1() {
    int i = blockIdx.x * blockDim.x + threadIdx.x;
    if (i >= N_EDGES) return;
    int2 e = __ldg(&g_edge[i]);
    float ns = __ldg(&g_norm_src[e.x]);
    const float4* t4 = (const float4*)(g_h1 + (size_t)e.x * NH);
    float4 v0 = __ldg(t4 + 0), v1 = __ldg(t4 + 1);
    float4 v2 = __ldg(t4 + 2), v3 = __ldg(t4 + 3);
    v0.x *= ns; v0.y *= ns; v0.z *= ns; v0.w *= ns;
    v1.x *= ns; v1.y *= ns; v1.z *= ns; v1.w *= ns;
    v2.x *= ns; v2.y *= ns; v2.z *= ns; v2.w *= ns;
    v3.x *= ns; v3.y *= ns; v3.z *= ns; v3.w *= ns;
    float* base = g_agg1 + (size_t)e.y * NH;
    red4(base + 0,  v0);
    red4(base + 4,  v1);
    red4(base + 8,  v2);
    red4(base + 12, v3);
}

// ---------------- W2f = W2 @ Wfc, b2f = b2 @ Wfc + bfc  (warp-parallel) ------
__global__ void k_w2f(const float* __restrict__ W2, const float* __restrict__ b2,
                      const float* __restrict__ Wfc, const float* __restrict__ bfc) {
    int w    = (blockIdx.x * blockDim.x + threadIdx.x) >> 5;
    int lane = threadIdx.x & 31;
    if (w < NH * NC) {
        int h = w / NC, c = w % NC;
        float s = 0.f;
        #pragma unroll
        for (int k = lane; k < 128; k += 32)
            s = fmaf(__ldg(W2 + h * 128 + k), __ldg(Wfc + k * NC + c), s);
        #pragma unroll
        for (int m = 16; m; m >>= 1) s += __shfl_xor_sync(0xffffffffu, s, m);
        if (lane == 0) g_W2f[w] = s;
    } else if (w < NH * NC + NC) {
        int c = w - NH * NC;
        float s = 0.f;
        #pragma unroll
        for (int k = lane; k < 128; k += 32)
            s = fmaf(__ldg(b2 + k), __ldg(Wfc + k * NC + c), s);
        #pragma unroll
        for (int m = 16; m; m >>= 1) s += __shfl_xor_sync(0xffffffffu, s, m);
        if (lane == 0) g_b2f[c] = s + __ldg(bfc + c);
    }
}

// ---------------- y = (relu(agg1*nd+b1)*ns) @ W2f  -> float4 (w=0) -----------
__global__ void k_y(const float* __restrict__ b1) {
    __shared__ float sw[NH * NC];
    if (threadIdx.x < NH * NC) sw[threadIdx.x] = g_W2f[threadIdx.x];
    __syncthreads();
    int n = blockIdx.x * blockDim.x + threadIdx.x;
    if (n >= N_NODES) return;
    const float4* a4 = (const float4*)(g_agg1 + (size_t)n * NH);
    float4 A[4] = {a4[0], a4[1], a4[2], a4[3]};
    const float* af = (const float*)A;
    float nd = g_norm_dst[n];
    float ns = g_norm_src[n];
    float s0 = 0.f, s1 = 0.f, s2 = 0.f;
    #pragma unroll
    for (int h = 0; h < NH; h++) {
        float x = fmaxf(fmaf(af[h], nd, __ldg(b1 + h)), 0.f) * ns;
        s0 = fmaf(x, sw[h * 3 + 0], s0);
        s1 = fmaf(x, sw[h * 3 + 1], s1);
        s2 = fmaf(x, sw[h * 3 + 2], s2);
    }
    ((float4*)g_y)[n] = make_float4(s0, s1, s2, 0.f);
}

// ---------------- edge pass 2: agg2[d] += y[s]  (1x RED.128) -----------------
__global__ void k_edge2() {
    int i = blockIdx.x * blockDim.x + threadIdx.x;
    if (i >= N_EDGES) return;
    int2 e = __ldg(&g_edge[i]);
    float4 v = __ldg((const float4*)g_y + e.x);
    red4(g_agg2 + (size_t)e.y * 4, v);
}

// ---------------- out = nd * agg2.xyz + b2f ----------------------------------
__global__ void k_out(float* __restrict__ out) {
    int n = blockIdx.x * blockDim.x + threadIdx.x;
    if (n >= N_NODES) return;
    float4 a = ((const float4*)g_agg2)[n];
    float nd = g_norm_dst[n];
    out[(size_t)n * 3 + 0] = fmaf(nd, a.x, g_b2f[0]);
    out[(size_t)n * 3 + 1] = fmaf(nd, a.y, g_b2f[1]);
    out[(size_t)n * 3 + 2] = fmaf(nd, a.z, g_b2f[2]);
}

// ---------------- launch ------------------------------------------------------
extern "C" void kernel_launch(void* const* d_in, const int* in_sizes, int n_in,
                              void* d_out, int out_size) {
    const float* feat = (const float*)d_in[0];
    const void*  src  = d_in[1];
    const void*  dst  = d_in[2];
    const float* W1   = (const float*)d_in[3];
    const float* b1   = (const float*)d_in[4];
    const float* W2   = (const float*)d_in[5];
    const float* b2   = (const float*)d_in[6];
    const float* Wfc  = (const float*)d_in[7];
    const float* bfc  = (const float*)d_in[8];
    float* out = (float*)d_out;

    static cudaStream_t s1 = nullptr;
    static cudaEvent_t  e0 = nullptr, e1 = nullptr;
    if (!s1) {
        cudaStreamCreateWithFlags(&s1, cudaStreamNonBlocking);
        cudaEventCreateWithFlags(&e0, cudaEventDisableTiming);
        cudaEventCreateWithFlags(&e1, cudaEventDisableTiming);
        cudaFuncSetAttribute(k_gemm1, cudaFuncAttributeMaxDynamicSharedMemorySize,
                             SMEM4);
    }

    const int EB = (N_EDGES + 255) / 256;            // 12500
    const int NB = (N_NODES + 255) / 256;            // 391
    const int GBLK = (N_NODES + GB4 - 1) / GB4;      // 782

    k_detect<<<1, 1>>>((const int*)src);             // #1
    cudaEventRecord(e0, 0);

    cudaStreamWaitEvent(s1, e0, 0);
    k_zero<<<(N_NODES * NH + 255) / 256, 256, 0, s1>>>();  // #2
    k_deg <<<2048, 256, 0, s1>>>(src, dst);                // #3

    k_gemm1<<<GBLK, 256, SMEM4>>>(feat, W1);               // #4  <- profiled

    k_norm<<<NB, 256, 0, s1>>>();                          // #5
    k_w2f <<<2, 1024, 0, s1>>>(W2, b2, Wfc, bfc);          // #6
    cudaEventRecord(e1, s1);

    cudaStreamWaitEvent(0, e1, 0);
    k_edge1<<<EB, 256>>>();                                // #7
    k_y    <<<NB, 256>>>(b1);                              // #8
    k_edge2<<<EB, 256>>>();                                // #9
    k_out  <<<NB, 256>>>(out);                             // #10
}

// round 17
// speedup vs baseline: 1.7581x; 1.0498x over previous
#include <cuda_runtime.h>

#define N_NODES 100000
#define N_EDGES 3200000
#define F_IN    512
#define NH      16
#define NC      3

// ---------------- scratch (device globals; device-code references ONLY) -----
__device__ int   g_deg_out[N_NODES];
__device__ int   g_deg_in [N_NODES];
__device__ int2  g_edge[N_EDGES];                 // packed (src,dst) int32
__device__ float g_h1  [(size_t)N_NODES * NH];    // feat@W1 (unscaled)
__device__ float g_agg1[(size_t)N_NODES * NH];
__device__ float g_y   [(size_t)N_NODES * 4];     // (relu(agg1*nd+b1)*ns)@W2f
__device__ float g_agg2[(size_t)N_NODES * 4];
__device__ float g_W2f [NH * NC];                 // W2 @ Wfc
__device__ float g_b2f [NC];                      // b2 @ Wfc + bfc

// ---------------- zero accumulators + degree counters (side stream) ----------
__global__ void k_zero() {
    int i = blockIdx.x * blockDim.x + threadIdx.x;
    if (i < N_NODES * NH) g_agg1[i] = 0.f;
    if (i < N_NODES * 4)  g_agg2[i] = 0.f;
    if (i < N_NODES) { g_deg_out[i] = 0; g_deg_in[i] = 0; }
}

// ---------------- degrees + edge compaction + inline int64/int32 detect ------
// int64 indices (values < 2^31) have all-zero odd 32-bit words; int32 edge ids
// are random node ids. One thread per block checks 64 odd words.
__global__ __launch_bounds__(256)
void k_deg(const void* __restrict__ src, const void* __restrict__ dst) {
    __shared__ int s_is64;
    if (threadIdx.x == 0) {
        int any = 0;
        #pragma unroll
        for (int j = 0; j < 64; j++) any |= ((const int*)src)[2 * j + 1];
        s_is64 = (any == 0);
    }
    __syncthreads();
    const int is64 = s_is64;
    int stride = gridDim.x * blockDim.x;
    for (int i = blockIdx.x * blockDim.x + threadIdx.x; i < N_EDGES; i += stride) {
        int s, d;
        if (is64) {
            s = (int)((const long long*)src)[i];
            d = (int)((const long long*)dst)[i];
        } else {
            s = ((const int*)src)[i];
            d = ((const int*)dst)[i];
        }
        g_edge[i] = make_int2(s, d);
        asm volatile("red.global.add.u32 [%0], %1;"
                     :: "l"(g_deg_out + s), "r"(1) : "memory");
        asm volatile("red.global.add.u32 [%0], %1;"
                     :: "l"(g_deg_in + d), "r"(1) : "memory");
    }
}

// ---------------- GEMM1: h1 = feat @ W1  (cp.async depth-2, broadcast W) ------
// 96 nodes/block, 256 thr = 8 warps; warp w owns k-slice [w*8,w*8+8) of each
// 64-wide chunk; lane covers nodes lane+32m (m=0..2). 3 staging buffers,
// wait_group 1 => compute chunk c overlaps the in-flight loads of chunk c+1.
#define GB4    96
#define PITCH4 17
#define BUF_F4 (GB4 * PITCH4)                      // 1632 float4 per buffer
#define RED_ST 18
#define SMEM4  ((F_IN * NH + 3 * BUF_F4 * 4) * 4)  // 32KB W + 76.5KB buf (red aliases)

__global__ __launch_bounds__(256, 2)
void k_gemm1(const float* __restrict__ feat, const float* __restrict__ W1) {
    extern __shared__ float smem[];
    float*  sW   = smem;                           // [512][16]
    float4* sF   = (float4*)(smem + F_IN * NH);    // 3 x [96][17] float4
    float*  sRed = smem + F_IN * NH;               // [8*96][18] (aliases sF)

    const int tid  = threadIdx.x;
    const int w    = tid >> 5;
    const int lane = tid & 31;
    const int n0   = blockIdx.x * GB4;

    #pragma unroll
    for (int t = tid; t < F_IN * NH / 4; t += 256)
        ((float4*)sW)[t] = ((const float4*)W1)[t];

    auto stage = [&](int c, int buf) {
        #pragma unroll
        for (int j = 0; j < 6; j++) {              // 96*16/256 = 6
            int f4idx = tid + 256 * j;
            int node  = f4idx >> 4;
            int c4    = f4idx & 15;
            int n     = n0 + node;
            const float* gsrc = feat +
                (size_t)(n < N_NODES ? n : 0) * F_IN + c * 64 + c4 * 4;
            unsigned sa = (unsigned)__cvta_generic_to_shared(
                &sF[buf * BUF_F4 + node * PITCH4 + c4]);
            int sz = (n < N_NODES) ? 16 : 0;
            asm volatile("cp.async.cg.shared.global [%0], [%1], 16, %2;"
                         :: "r"(sa), "l"(gsrc), "r"(sz) : "memory");
        }
        asm volatile("cp.async.commit_group;" ::: "memory");
    };

    stage(0, 0);
    stage(1, 1);

    unsigned long long A[3][8];
    #pragma unroll
    for (int m = 0; m < 3; m++)
        #pragma unroll
        for (int p = 0; p < 8; p++) A[m][p] = 0ull;

    #pragma unroll
    for (int c = 0; c < 8; c++) {
        if (c < 6) { asm volatile("cp.async.wait_group 1;" ::: "memory"); }
        else       { asm volatile("cp.async.wait_group 0;" ::: "memory"); }
        __syncthreads();                           // buf c ready; all warps past c-1
        if (c + 2 < 8) stage(c + 2, (c + 2) % 3);  // overwrites buf (c-1)%3: safe

        const float4* fb = sF + (c % 3) * BUF_F4;
        #pragma unroll
        for (int c4i = 0; c4i < 2; c4i++) {
            const int c4 = w * 2 + c4i;
            float f[3][4];
            #pragma unroll
            for (int m = 0; m < 3; m++) {
                float4 v = fb[(lane + 32 * m) * PITCH4 + c4];
                f[m][0] = v.x; f[m][1] = v.y; f[m][2] = v.z; f[m][3] = v.w;
            }
            const float* wk = sW + (size_t)(c * 64 + c4 * 4) * NH;
            #pragma unroll
            for (int kk = 0; kk < 4; kk++) {
                const ulonglong2* wp = (const ulonglong2*)(wk + kk * NH);
                ulonglong2 w0 = wp[0], w1 = wp[1];
                const ulonglong2* wq = (const ulonglong2*)(wk + kk * NH + 8);
                ulonglong2 w2 = wq[0], w3 = wq[1];
                #pragma unroll
                for (int m = 0; m < 3; m++) {
                    unsigned long long fp;
                    asm("mov.b64 %0, {%1, %1};" : "=l"(fp) : "f"(f[m][kk]));
                    asm("fma.rn.f32x2 %0, %1, %2, %0;" : "+l"(A[m][0]) : "l"(fp), "l"(w0.x));
                    asm("fma.rn.f32x2 %0, %1, %2, %0;" : "+l"(A[m][1]) : "l"(fp), "l"(w0.y));
                    asm("fma.rn.f32x2 %0, %1, %2, %0;" : "+l"(A[m][2]) : "l"(fp), "l"(w1.x));
                    asm("fma.rn.f32x2 %0, %1, %2, %0;" : "+l"(A[m][3]) : "l"(fp), "l"(w1.y));
                    asm("fma.rn.f32x2 %0, %1, %2, %0;" : "+l"(A[m][4]) : "l"(fp), "l"(w2.x));
                    asm("fma.rn.f32x2 %0, %1, %2, %0;" : "+l"(A[m][5]) : "l"(fp), "l"(w2.y));
                    asm("fma.rn.f32x2 %0, %1, %2, %0;" : "+l"(A[m][6]) : "l"(fp), "l"(w3.x));
                    asm("fma.rn.f32x2 %0, %1, %2, %0;" : "+l"(A[m][7]) : "l"(fp), "l"(w3.y));
                }
            }
        }
        __syncthreads();
    }

    // cross-warp reduce (sRed aliases staging buffers; compute is done)
    #pragma unroll
    for (int m = 0; m < 3; m++) {
        float* dst = sRed + (size_t)(w * GB4 + lane + 32 * m) * RED_ST;
        #pragma unroll
        for (int p = 0; p < 8; p++)
            *(float2*)&dst[2 * p] = *(float2*)&A[m][p];
    }
    __syncthreads();
    #pragma unroll
    for (int t = tid; t < GB4 * 8; t += 256) {
        int node = t >> 3, p = t & 7;
        float sx = 0.f, sy = 0.f;
        #pragma unroll
        for (int ww = 0; ww < 8; ww++) {
            float2 v = *(float2*)&sRed[(size_t)(ww * GB4 + node) * RED_ST + 2 * p];
            sx += v.x; sy += v.y;
        }
        int n = n0 + node;
        if (n < N_NODES)
            *(float2*)&g_h1[(size_t)n * NH + 2 * p] = make_float2(sx, sy);
    }
}

// ---------------- edge pass 1: agg1[d] += ns[s]*h1[s]  (4x RED.128) ----------
// norm_src computed inline from deg_out (MUFU hidden under atomic issue).
__device__ __forceinline__ void red4(float* p, float4 v) {
    asm volatile("red.global.add.v4.f32 [%0], {%1,%2,%3,%4};"
                 :: "l"(p), "f"(v.x), "f"(v.y), "f"(v.z), "f"(v.w) : "memory");
}

__global__ void k_edge1() {
    int i = blockIdx.x * blockDim.x + threadIdx.x;
    if (i >= N_EDGES) return;
    int2 e = __ldg(&g_edge[i]);
    float ns = rsqrtf(fmaxf((float)__ldg(&g_deg_out[e.x]), 1.f));
    const float4* t4 = (const float4*)(g_h1 + (size_t)e.x * NH);
    float4 v0 = __ldg(t4 + 0), v1 = __ldg(t4 + 1);
    float4 v2 = __ldg(t4 + 2), v3 = __ldg(t4 + 3);
    v0.x *= ns; v0.y *= ns; v0.z *= ns; v0.w *= ns;
    v1.x *= ns; v1.y *= ns; v1.z *= ns; v1.w *= ns;
    v2.x *= ns; v2.y *= ns; v2.z *= ns; v2.w *= ns;
    v3.x *= ns; v3.y *= ns; v3.z *= ns; v3.w *= ns;
    float* base = g_agg1 + (size_t)e.y * NH;
    red4(base + 0,  v0);
    red4(base + 4,  v1);
    red4(base + 8,  v2);
    red4(base + 12, v3);
}

// ---------------- W2f = W2 @ Wfc, b2f = b2 @ Wfc + bfc  (warp-parallel) ------
__global__ void k_w2f(const float* __restrict__ W2, const float* __restrict__ b2,
                      const float* __restrict__ Wfc, const float* __restrict__ bfc) {
    int w    = (blockIdx.x * blockDim.x + threadIdx.x) >> 5;
    int lane = threadIdx.x & 31;
    if (w < NH * NC) {
        int h = w / NC, c = w % NC;
        float s = 0.f;
        #pragma unroll
        for (int k = lane; k < 128; k += 32)
            s = fmaf(__ldg(W2 + h * 128 + k), __ldg(Wfc + k * NC + c), s);
        #pragma unroll
        for (int m = 16; m; m >>= 1) s += __shfl_xor_sync(0xffffffffu, s, m);
        if (lane == 0) g_W2f[w] = s;
    } else if (w < NH * NC + NC) {
        int c = w - NH * NC;
        float s = 0.f;
        #pragma unroll
        for (int k = lane; k < 128; k += 32)
            s = fmaf(__ldg(b2 + k), __ldg(Wfc + k * NC + c), s);
        #pragma unroll
        for (int m = 16; m; m >>= 1) s += __shfl_xor_sync(0xffffffffu, s, m);
        if (lane == 0) g_b2f[c] = s + __ldg(bfc + c);
    }
}

// ---------------- y = (relu(agg1*nd+b1)*ns) @ W2f  -> float4 (w=0) -----------
__global__ void k_y(const float* __restrict__ b1) {
    __shared__ float sw[NH * NC];
    if (threadIdx.x < NH * NC) sw[threadIdx.x] = g_W2f[threadIdx.x];
    __syncthreads();
    int n = blockIdx.x * blockDim.x + threadIdx.x;
    if (n >= N_NODES) return;
    const float4* a4 = (const float4*)(g_agg1 + (size_t)n * NH);
    float4 A[4] = {a4[0], a4[1], a4[2], a4[3]};
    const float* af = (const float*)A;
    float nd = rsqrtf(fmaxf((float)g_deg_in [n], 1.f));
    float ns = rsqrtf(fmaxf((float)g_deg_out[n], 1.f));
    float s0 = 0.f, s1 = 0.f, s2 = 0.f;
    #pragma unroll
    for (int h = 0; h < NH; h++) {
        float x = fmaxf(fmaf(af[h], nd, __ldg(b1 + h)), 0.f) * ns;
        s0 = fmaf(x, sw[h * 3 + 0], s0);
        s1 = fmaf(x, sw[h * 3 + 1], s1);
        s2 = fmaf(x, sw[h * 3 + 2], s2);
    }
    ((float4*)g_y)[n] = make_float4(s0, s1, s2, 0.f);
}

// ---------------- edge pass 2: agg2[d] += y[s]  (1x RED.128) -----------------
__global__ void k_edge2() {
    int i = blockIdx.x * blockDim.x + threadIdx.x;
    if (i >= N_EDGES) return;
    int2 e = __ldg(&g_edge[i]);
    float4 v = __ldg((const float4*)g_y + e.x);
    red4(g_agg2 + (size_t)e.y * 4, v);
}

// ---------------- out = nd * agg2.xyz + b2f ----------------------------------
__global__ void k_out(float* __restrict__ out) {
    int n = blockIdx.x * blockDim.x + threadIdx.x;
    if (n >= N_NODES) return;
    float4 a = ((const float4*)g_agg2)[n];
    float nd = rsqrtf(fmaxf((float)g_deg_in[n], 1.f));
    out[(size_t)n * 3 + 0] = fmaf(nd, a.x, g_b2f[0]);
    out[(size_t)n * 3 + 1] = fmaf(nd, a.y, g_b2f[1]);
    out[(size_t)n * 3 + 2] = fmaf(nd, a.z, g_b2f[2]);
}

// ---------------- launch ------------------------------------------------------
extern "C" void kernel_launch(void* const* d_in, const int* in_sizes, int n_in,
                              void* d_out, int out_size) {
    const float* feat = (const float*)d_in[0];
    const void*  src  = d_in[1];
    const void*  dst  = d_in[2];
    const float* W1   = (const float*)d_in[3];
    const float* b1   = (const float*)d_in[4];
    const float* W2   = (const float*)d_in[5];
    const float* b2   = (const float*)d_in[6];
    const float* Wfc  = (const float*)d_in[7];
    const float* bfc  = (const float*)d_in[8];
    float* out = (float*)d_out;

    static cudaStream_t s1 = nullptr;
    static cudaEvent_t  e0 = nullptr, e1 = nullptr, e2 = nullptr;
    if (!s1) {
        cudaStreamCreateWithFlags(&s1, cudaStreamNonBlocking);
        cudaEventCreateWithFlags(&e0, cudaEventDisableTiming);
        cudaEventCreateWithFlags(&e1, cudaEventDisableTiming);
        cudaEventCreateWithFlags(&e2, cudaEventDisableTiming);
        cudaFuncSetAttribute(k_gemm1, cudaFuncAttributeMaxDynamicSharedMemorySize,
                             SMEM4);
    }

    const int EB = (N_EDGES + 255) / 256;            // 12500
    const int NB = (N_NODES + 255) / 256;            // 391
    const int GBLK = (N_NODES + GB4 - 1) / GB4;      // 1042

    // FORK: side stream must join capture via an event recorded on the
    // capture stream BEFORE any launch on it (this was the R16 failure).
    cudaEventRecord(e0, 0);
    cudaStreamWaitEvent(s1, e0, 0);

    // side stream: zero + deg/pack (overlaps gemm1)
    k_zero<<<(N_NODES * NH + 255) / 256, 256, 0, s1>>>();  // kernel #1
    k_deg <<<2048, 256, 0, s1>>>(src, dst);                // kernel #2
    cudaEventRecord(e1, s1);

    // main stream
    k_gemm1<<<GBLK, 256, SMEM4>>>(feat, W1);               // kernel #3
    cudaStreamWaitEvent(0, e1, 0);
    k_edge1<<<EB, 256>>>();                                // kernel #4 <- profiled

    k_w2f<<<2, 1024, 0, s1>>>(W2, b2, Wfc, bfc);           // kernel #5 (side)
    cudaEventRecord(e2, s1);
    cudaStreamWaitEvent(0, e2, 0);

    k_y    <<<NB, 256>>>(b1);                              // kernel #6
    k_edge2<<<EB, 256>>>();                                // kernel #7
    k_out  <<<NB, 256>>>(out);                             // kernel #8
}